// round 12
// baseline (speedup 1.0000x reference)
#include <cuda_runtime.h>
#include <cuda_fp16.h>
#include <math.h>

#define NN 100000
#define NE 1600000
#define KT 25
#define XW_COLS 800   // KT*32

// ---------------- scratch (__device__ globals) ----------------
__device__ __half g_xw[(size_t)NN * XW_COLS];   // fp16 table, 160 MB
__device__ float g_xroot[NN * 32];
__device__ float g_rdot[NN];
__device__ float g_denom[NN];
__device__ int   g_sink;

// ---------------- f32x2 helpers ----------------
__device__ __forceinline__ void ffma2(unsigned long long& acc, unsigned long long a,
                                      unsigned long long b) {
    asm("fma.rn.f32x2 %0, %1, %2, %0;" : "+l"(acc) : "l"(a), "l"(b));
}
__device__ __forceinline__ unsigned long long pack2(float x, float y) {
    unsigned long long r;
    asm("mov.b64 %0, {%1,%2};" : "=l"(r) : "f"(x), "f"(y));
    return r;
}
__device__ __forceinline__ float2 unpack2(unsigned long long v) {
    float2 r;
    asm("mov.b64 {%0,%1}, %2;" : "=f"(r.x), "=f"(r.y) : "l"(v));
    return r;
}

// ---------------- K_root: x_root = x@rw, rdot, init accumulators ----------------
__global__ void k_root(const float* __restrict__ x, const float* __restrict__ rw,
                       const float* __restrict__ att, float* __restrict__ out) {
    __shared__ float rws[1024];
    __shared__ float atts[32];
    int tid = threadIdx.x;
    for (int i = tid; i < 1024; i += 256) rws[i] = rw[i];
    if (tid < 32) atts[tid] = att[tid];
    __syncthreads();
    int warp = tid >> 5, lane = tid & 31;
    int n = blockIdx.x * 8 + warp;          // 12500*8 = 100000 exact
    float xv = x[n * 32 + lane];
    float acc = 0.f;
#pragma unroll
    for (int f = 0; f < 32; f++) {
        float xf = __shfl_sync(0xffffffffu, xv, f);
        acc = fmaf(xf, rws[f * 32 + lane], acc);
    }
    g_xroot[n * 32 + lane] = acc;
    out[n * 32 + lane] = 0.f;               // zero edge accumulator
    float t = acc * atts[lane];
#pragma unroll
    for (int o = 16; o; o >>= 1) t += __shfl_xor_sync(0xffffffffu, t, o);
    if (lane == 0) { g_rdot[n] = t; g_denom[n] = 0.f; }
}

// ---------------- K_xw: g_xw[n][k*32+o] = sum_f x[n][f]*W[k][f][o]  (fp16 out) ----
#define KB_STRIDE 1026
#define NKB 28
#define XS_STRIDE 33
#define WS_FLOATS (NKB * KB_STRIDE)    // 28728
#define K_XW_SMEM ((WS_FLOATS + 128 * XS_STRIDE) * 4)

__global__ void __launch_bounds__(256) k_xw(const float* __restrict__ x,
                                            const float* __restrict__ w) {
    extern __shared__ float sm[];
    float* Ws = sm;                    // [kb*1026 + f*32 + o]
    float* xs = sm + WS_FLOATS;        // [node_local*33 + f]
    int tid = threadIdx.x;
    int n0 = blockIdx.x * 128;

    for (int kb = 0; kb < NKB; kb++) {
        for (int i2 = tid; i2 < 513; i2 += 256) {
            float2 v = (kb < KT && i2 < 512) ? ((const float2*)w)[kb * 512 + i2]
                                             : make_float2(0.f, 0.f);
            *(float2*)&Ws[kb * KB_STRIDE + i2 * 2] = v;
        }
    }
    for (int i = tid; i < 128 * 32; i += 256) {
        int n = i >> 5, f = i & 31;
        int gn = n0 + n;
        xs[n * XS_STRIDE + f] = (gn < NN) ? x[gn * 32 + f] : 0.f;
    }
    __syncthreads();

    int tx = tid & 15, ty = tid >> 4;
    int coff = (tx * 8) & 31;

    for (int cc = 0; cc < 7; cc++) {
        int col0 = cc * 128 + tx * 8;
        int base = (col0 >> 5) * KB_STRIDE + coff;

        unsigned long long acc[8][4];
#pragma unroll
        for (int j = 0; j < 8; j++)
#pragma unroll
            for (int i = 0; i < 4; i++) acc[j][i] = 0ull;

#pragma unroll
        for (int f = 0; f < 32; f++) {
            unsigned long long wp[4];
#pragma unroll
            for (int i = 0; i < 4; i++) {
                float2 w2 = *(const float2*)&Ws[base + f * 32 + 2 * i];
                wp[i] = pack2(w2.x, w2.y);
            }
#pragma unroll
            for (int j = 0; j < 8; j++) {
                float xv = xs[(ty * 8 + j) * XS_STRIDE + f];
                unsigned long long xp = pack2(xv, xv);
#pragma unroll
                for (int i = 0; i < 4; i++) ffma2(acc[j][i], xp, wp[i]);
            }
        }

        if (col0 < XW_COLS) {
#pragma unroll
            for (int j = 0; j < 8; j++) {
                int n = n0 + ty * 8 + j;
                if (n < NN) {
                    uint4 v;
                    float2 p0 = unpack2(acc[j][0]);
                    float2 p1 = unpack2(acc[j][1]);
                    float2 p2 = unpack2(acc[j][2]);
                    float2 p3 = unpack2(acc[j][3]);
                    __half2 h0 = __floats2half2_rn(p0.x, p0.y);
                    __half2 h1 = __floats2half2_rn(p1.x, p1.y);
                    __half2 h2 = __floats2half2_rn(p2.x, p2.y);
                    __half2 h3 = __floats2half2_rn(p3.x, p3.y);
                    v.x = *(unsigned int*)&h0;
                    v.y = *(unsigned int*)&h1;
                    v.z = *(unsigned int*)&h2;
                    v.w = *(unsigned int*)&h3;
                    *(uint4*)(g_xw + (size_t)n * XW_COLS + col0) = v;
                }
            }
        }
    }
}

// ---------------- dummy: occupies profile slot 3 so k_edge lands at slot 4 ----
__global__ void k_dummy() { g_sink = 0; }

// ---------------- K_edge: 2 edges per thread, 8 lanes/edge ----------------
// lane q owns output features [4q, 4q+4) of both edges; all 8 gathers issued
// before any dependent math -> doubled MLP per warp.
__global__ void __launch_bounds__(256) k_edge(const int* __restrict__ ei,
                                              const float* __restrict__ ps,
                                              const float* __restrict__ att,
                                              float* __restrict__ out) {
    int gid = blockIdx.x * 256 + threadIdx.x;   // 25000*256 = 6.4M = NE*8/2
    int ep = gid >> 3;                           // edge pair index
    int q = gid & 7;
    int eA = ep * 2;

    int2 rows = __ldg((const int2*)(ei) + ep);
    int2 cols = __ldg((const int2*)(ei + NE) + ep);
    float4 pp = __ldg((const float4*)(ps) + ep);

    // ---- spline params, edge A ----
    float pa0 = pp.x * 4.f, pa1 = pp.y * 4.f;
    float fla0 = floorf(pa0), fla1 = floorf(pa1);
    float fra0 = pa0 - fla0, fra1 = pa1 - fla1;
    int ia0 = max(0, min(3, (int)fla0));
    int ia1 = max(0, min(3, (int)fla1));
    float ab0 = (1.f - fra0) * (1.f - fra1);
    float ab1 = fra0 * (1.f - fra1);
    float ab2 = (1.f - fra0) * fra1;
    float ab3 = fra0 * fra1;
    int wa = ia0 + 5 * ia1;

    // ---- spline params, edge B ----
    float pb0 = pp.z * 4.f, pb1 = pp.w * 4.f;
    float flb0 = floorf(pb0), flb1 = floorf(pb1);
    float frb0 = pb0 - flb0, frb1 = pb1 - flb1;
    int ib0 = max(0, min(3, (int)flb0));
    int ib1 = max(0, min(3, (int)flb1));
    float bb0 = (1.f - frb0) * (1.f - frb1);
    float bb1 = frb0 * (1.f - frb1);
    float bb2 = (1.f - frb0) * frb1;
    float bb3 = frb0 * frb1;
    int wb = ib0 + 5 * ib1;

    // ---- issue all 8 gathers up-front (uint2 = 4 halves each) ----
    const uint2* tb = (const uint2*)g_xw;
    size_t na = (size_t)cols.x * 200 + q;
    size_t nbs = (size_t)cols.y * 200 + q;
    uint2 ua0 = __ldg(tb + na + (size_t)wa * 8);
    uint2 ua1 = __ldg(tb + na + (size_t)(wa + 1) * 8);
    uint2 ua2 = __ldg(tb + na + (size_t)(wa + 5) * 8);
    uint2 ua3 = __ldg(tb + na + (size_t)(wa + 6) * 8);
    uint2 ub0 = __ldg(tb + nbs + (size_t)wb * 8);
    uint2 ub1 = __ldg(tb + nbs + (size_t)(wb + 1) * 8);
    uint2 ub2 = __ldg(tb + nbs + (size_t)(wb + 5) * 8);
    uint2 ub3 = __ldg(tb + nbs + (size_t)(wb + 6) * 8);

    float rdA = __ldg(&g_rdot[rows.x]);
    float rdB = __ldg(&g_rdot[rows.y]);
    float4 av = __ldg(reinterpret_cast<const float4*>(att + 32) + q);

    // ---- edge A message ----
    float2 a0 = __half22float2(*(__half2*)&ua0.x), a1 = __half22float2(*(__half2*)&ua0.y);
    float2 c0 = __half22float2(*(__half2*)&ua1.x), c1 = __half22float2(*(__half2*)&ua1.y);
    float2 d0 = __half22float2(*(__half2*)&ua2.x), d1 = __half22float2(*(__half2*)&ua2.y);
    float2 e0 = __half22float2(*(__half2*)&ua3.x), e1 = __half22float2(*(__half2*)&ua3.y);
    float4 mA;
    mA.x = ab0 * a0.x + ab1 * c0.x + ab2 * d0.x + ab3 * e0.x;
    mA.y = ab0 * a0.y + ab1 * c0.y + ab2 * d0.y + ab3 * e0.y;
    mA.z = ab0 * a1.x + ab1 * c1.x + ab2 * d1.x + ab3 * e1.x;
    mA.w = ab0 * a1.y + ab1 * c1.y + ab2 * d1.y + ab3 * e1.y;

    // ---- edge B message ----
    float2 f0 = __half22float2(*(__half2*)&ub0.x), f1 = __half22float2(*(__half2*)&ub0.y);
    float2 g0 = __half22float2(*(__half2*)&ub1.x), g1 = __half22float2(*(__half2*)&ub1.y);
    float2 h0 = __half22float2(*(__half2*)&ub2.x), h1 = __half22float2(*(__half2*)&ub2.y);
    float2 i0f = __half22float2(*(__half2*)&ub3.x), i1f = __half22float2(*(__half2*)&ub3.y);
    float4 mB;
    mB.x = bb0 * f0.x + bb1 * g0.x + bb2 * h0.x + bb3 * i0f.x;
    mB.y = bb0 * f0.y + bb1 * g0.y + bb2 * h0.y + bb3 * i0f.y;
    mB.z = bb0 * f1.x + bb1 * g1.x + bb2 * h1.x + bb3 * i1f.x;
    mB.w = bb0 * f1.y + bb1 * g1.y + bb2 * h1.y + bb3 * i1f.y;

    // ---- attention logits (both chains interleave) ----
    float tA = mA.x * av.x + mA.y * av.y + mA.z * av.z + mA.w * av.w;
    float tB = mB.x * av.x + mB.y * av.y + mB.z * av.z + mB.w * av.w;
    tA += __shfl_xor_sync(0xffffffffu, tA, 1);
    tB += __shfl_xor_sync(0xffffffffu, tB, 1);
    tA += __shfl_xor_sync(0xffffffffu, tA, 2);
    tB += __shfl_xor_sync(0xffffffffu, tB, 2);
    tA += __shfl_xor_sync(0xffffffffu, tA, 4);
    tB += __shfl_xor_sync(0xffffffffu, tB, 4);

    float alA = rdA + tA;
    float alB = rdB + tB;
    alA = alA > 0.f ? alA : 0.2f * alA;
    alB = alB > 0.f ? alB : 0.2f * alB;
    float exA = __expf(alA);
    float exB = __expf(alB);
    if (q == 0) {
        atomicAdd(&g_denom[rows.x], exA);
        atomicAdd(&g_denom[rows.y], exB);
    }

    float* opA = out + rows.x * 32 + q * 4;
    asm volatile("red.global.add.v4.f32 [%0], {%1,%2,%3,%4};" ::
                 "l"(opA), "f"(mA.x * exA), "f"(mA.y * exA), "f"(mA.z * exA), "f"(mA.w * exA)
                 : "memory");
    float* opB = out + rows.y * 32 + q * 4;
    asm volatile("red.global.add.v4.f32 [%0], {%1,%2,%3,%4};" ::
                 "l"(opB), "f"(mB.x * exB), "f"(mB.y * exB), "f"(mB.z * exB), "f"(mB.w * exB)
                 : "memory");
    (void)eA;
}

// ---------------- K_fin ----------------
__global__ void k_fin(float* __restrict__ out, const float* __restrict__ bias) {
    int i = blockIdx.x * 256 + threadIdx.x;  // 12500*256 = 3.2M exact
    int n = i >> 5, o = i & 31;
    out[i] = out[i] / (g_denom[n] + 1e-16f) + g_xroot[i] + bias[o];
}

// ---------------- launch ----------------
extern "C" void kernel_launch(void* const* d_in, const int* in_sizes, int n_in,
                              void* d_out, int out_size) {
    const float* x    = (const float*)d_in[0];
    const int*   ei   = (const int*)  d_in[1];
    const float* ps   = (const float*)d_in[2];
    const float* w    = (const float*)d_in[3];
    const float* rw   = (const float*)d_in[4];
    const float* att  = (const float*)d_in[5];
    const float* bias = (const float*)d_in[6];
    float* out = (float*)d_out;

    cudaFuncSetAttribute(k_xw, cudaFuncAttributeMaxDynamicSharedMemorySize, K_XW_SMEM);

    k_root<<<NN / 8, 256>>>(x, rw, att, out);            // launch 1
    k_xw<<<(NN + 127) / 128, 256, K_XW_SMEM>>>(x, w);    // launch 2
    k_dummy<<<1, 1>>>();                                 // launch 3 (profile spacer)
    k_edge<<<(NE * 8 / 2) / 256, 256>>>(ei, ps, att, out); // launch 4 <- profiled
    k_fin<<<(NN * 32) / 256, 256>>>(out, bias);          // launch 5
}

// round 17
// speedup vs baseline: 1.1901x; 1.1901x over previous
#include <cuda_runtime.h>
#include <cuda_fp16.h>
#include <math.h>

#define NN 100000
#define NE 1600000
#define KT 25
#define XW_COLS 800   // KT*32

// ---------------- scratch (__device__ globals) ----------------
__device__ __half g_xw[(size_t)NN * XW_COLS];   // fp16 table, 160 MB
__device__ float g_xroot[NN * 32];
__device__ float g_rdot[NN];
__device__ float g_denom[NN];
__device__ int   g_sink;

// ---------------- f32x2 helpers ----------------
__device__ __forceinline__ void ffma2(unsigned long long& acc, unsigned long long a,
                                      unsigned long long b) {
    asm("fma.rn.f32x2 %0, %1, %2, %0;" : "+l"(acc) : "l"(a), "l"(b));
}
__device__ __forceinline__ unsigned long long pack2(float x, float y) {
    unsigned long long r;
    asm("mov.b64 %0, {%1,%2};" : "=l"(r) : "f"(x), "f"(y));
    return r;
}
__device__ __forceinline__ float2 unpack2(unsigned long long v) {
    float2 r;
    asm("mov.b64 {%0,%1}, %2;" : "=f"(r.x), "=f"(r.y) : "l"(v));
    return r;
}

// ---------------- K_root: x_root = x@rw, rdot, init accumulators ----------------
__global__ void k_root(const float* __restrict__ x, const float* __restrict__ rw,
                       const float* __restrict__ att, float* __restrict__ out) {
    __shared__ float rws[1024];
    __shared__ float atts[32];
    int tid = threadIdx.x;
    for (int i = tid; i < 1024; i += 256) rws[i] = rw[i];
    if (tid < 32) atts[tid] = att[tid];
    __syncthreads();
    int warp = tid >> 5, lane = tid & 31;
    int n = blockIdx.x * 8 + warp;          // 12500*8 = 100000 exact
    float xv = x[n * 32 + lane];
    float acc = 0.f;
#pragma unroll
    for (int f = 0; f < 32; f++) {
        float xf = __shfl_sync(0xffffffffu, xv, f);
        acc = fmaf(xf, rws[f * 32 + lane], acc);
    }
    g_xroot[n * 32 + lane] = acc;
    out[n * 32 + lane] = 0.f;               // zero edge accumulator
    float t = acc * atts[lane];
#pragma unroll
    for (int o = 16; o; o >>= 1) t += __shfl_xor_sync(0xffffffffu, t, o);
    if (lane == 0) { g_rdot[n] = t; g_denom[n] = 0.f; }
}

// ---------------- K_xw: split-phase for 2 blocks/SM ----------------
// g_xw[n][k*32+o] = sum_f x[n][f]*W[k][f][o], fp16 out.
// Phase 0: kb 0..15 in smem, compute cols 0..511 (cc 0..3)
// Phase 1: kb 16..27 in smem, compute cols 512..895 (cc 4..6)
#define KB_STRIDE 1026
#define XS_STRIDE 33
#define WS_FLOATS (16 * KB_STRIDE)     // 16416 floats, peak W residency
#define K_XW_SMEM ((WS_FLOATS + 128 * XS_STRIDE) * 4)   // ~82.6 KB

__global__ void __launch_bounds__(256, 2) k_xw(const float* __restrict__ x,
                                               const float* __restrict__ w) {
    extern __shared__ float sm[];
    float* Ws = sm;                    // [kb_local*1026 + f*32 + o]
    float* xs = sm + WS_FLOATS;        // [node_local*33 + f]
    int tid = threadIdx.x;
    int n0 = blockIdx.x * 128;

    // fill x slice (once)
    for (int i = tid; i < 128 * 32; i += 256) {
        int n = i >> 5, f = i & 31;
        int gn = n0 + n;
        xs[n * XS_STRIDE + f] = (gn < NN) ? x[gn * 32 + f] : 0.f;
    }

    int tx = tid & 15, ty = tid >> 4;
    int coff = (tx * 8) & 31;

#pragma unroll
    for (int ph = 0; ph < 2; ph++) {
        int kb0 = ph ? 16 : 0;
        int nkb = ph ? 12 : 16;

        __syncthreads();               // protect prior-phase reads before overwrite
        for (int kb = 0; kb < nkb; kb++) {
            int gkb = kb0 + kb;
            for (int i2 = tid; i2 < 513; i2 += 256) {
                float2 v = (gkb < KT && i2 < 512) ? ((const float2*)w)[gkb * 512 + i2]
                                                  : make_float2(0.f, 0.f);
                *(float2*)&Ws[kb * KB_STRIDE + i2 * 2] = v;
            }
        }
        __syncthreads();

        int ccs = ph ? 4 : 0, cce = ph ? 7 : 4;
        for (int cc = ccs; cc < cce; cc++) {
            int col0 = cc * 128 + tx * 8;
            int base = ((col0 >> 5) - kb0) * KB_STRIDE + coff;

            unsigned long long acc[8][4];
#pragma unroll
            for (int j = 0; j < 8; j++)
#pragma unroll
                for (int i = 0; i < 4; i++) acc[j][i] = 0ull;

#pragma unroll
            for (int f = 0; f < 32; f++) {
                unsigned long long wp[4];
#pragma unroll
                for (int i = 0; i < 4; i++) {
                    float2 w2 = *(const float2*)&Ws[base + f * 32 + 2 * i];
                    wp[i] = pack2(w2.x, w2.y);
                }
#pragma unroll
                for (int j = 0; j < 8; j++) {
                    float xv = xs[(ty * 8 + j) * XS_STRIDE + f];
                    unsigned long long xp = pack2(xv, xv);
#pragma unroll
                    for (int i = 0; i < 4; i++) ffma2(acc[j][i], xp, wp[i]);
                }
            }

            if (col0 < XW_COLS) {
#pragma unroll
                for (int j = 0; j < 8; j++) {
                    int n = n0 + ty * 8 + j;
                    if (n < NN) {
                        uint4 v;
                        float2 p0 = unpack2(acc[j][0]);
                        float2 p1 = unpack2(acc[j][1]);
                        float2 p2 = unpack2(acc[j][2]);
                        float2 p3 = unpack2(acc[j][3]);
                        __half2 h0 = __floats2half2_rn(p0.x, p0.y);
                        __half2 h1 = __floats2half2_rn(p1.x, p1.y);
                        __half2 h2 = __floats2half2_rn(p2.x, p2.y);
                        __half2 h3 = __floats2half2_rn(p3.x, p3.y);
                        v.x = *(unsigned int*)&h0;
                        v.y = *(unsigned int*)&h1;
                        v.z = *(unsigned int*)&h2;
                        v.w = *(unsigned int*)&h3;
                        *(uint4*)(g_xw + (size_t)n * XW_COLS + col0) = v;
                    }
                }
            }
        }
    }
}

// ---------------- dummies: steer k_xw into profile slot 4 ----------------
__global__ void k_dummy() { g_sink = 0; }

// ---------------- K_edge: R8 form — 1 edge per 8-lane group ----------------
__global__ void k_edge(const int* __restrict__ ei, const float* __restrict__ ps,
                       const float* __restrict__ att, float* __restrict__ out) {
    int gid = blockIdx.x * 256 + threadIdx.x;   // 50000*256 = NE*8 exact
    int e = gid >> 3, q = gid & 7;
    int row = ei[e];
    int col = ei[NE + e];
    float2 p = *reinterpret_cast<const float2*>(ps + 2 * e);
    float p0 = p.x * 4.f, p1 = p.y * 4.f;
    float fl0 = floorf(p0), fl1 = floorf(p1);
    float fr0 = p0 - fl0, fr1 = p1 - fl1;
    int i0 = max(0, min(3, (int)fl0));
    int i1 = max(0, min(3, (int)fl1));
    float b0 = (1.f - fr0) * (1.f - fr1);
    float b1 = fr0 * (1.f - fr1);
    float b2 = (1.f - fr0) * fr1;
    float b3 = fr0 * fr1;
    int w0 = i0 + 5 * i1;   // corners: w0, w0+1, w0+5, w0+6

    const uint2* tb = (const uint2*)g_xw;       // uint2 = 4 halves
    size_t nb = (size_t)col * 200 + q;
    uint2 u0 = __ldg(tb + nb + (size_t)w0 * 8);
    uint2 u1 = __ldg(tb + nb + (size_t)(w0 + 1) * 8);
    uint2 u2 = __ldg(tb + nb + (size_t)(w0 + 5) * 8);
    uint2 u3 = __ldg(tb + nb + (size_t)(w0 + 6) * 8);

    float2 a0 = __half22float2(*(__half2*)&u0.x), a1 = __half22float2(*(__half2*)&u0.y);
    float2 c0 = __half22float2(*(__half2*)&u1.x), c1 = __half22float2(*(__half2*)&u1.y);
    float2 d0 = __half22float2(*(__half2*)&u2.x), d1 = __half22float2(*(__half2*)&u2.y);
    float2 e0 = __half22float2(*(__half2*)&u3.x), e1 = __half22float2(*(__half2*)&u3.y);

    float4 m;
    m.x = b0 * a0.x + b1 * c0.x + b2 * d0.x + b3 * e0.x;
    m.y = b0 * a0.y + b1 * c0.y + b2 * d0.y + b3 * e0.y;
    m.z = b0 * a1.x + b1 * c1.x + b2 * d1.x + b3 * e1.x;
    m.w = b0 * a1.y + b1 * c1.y + b2 * d1.y + b3 * e1.y;

    float4 av = __ldg(reinterpret_cast<const float4*>(att + 32) + q);
    float t = m.x * av.x + m.y * av.y + m.z * av.z + m.w * av.w;
    t += __shfl_xor_sync(0xffffffffu, t, 1);
    t += __shfl_xor_sync(0xffffffffu, t, 2);
    t += __shfl_xor_sync(0xffffffffu, t, 4);

    float alpha = __ldg(&g_rdot[row]) + t;
    alpha = alpha > 0.f ? alpha : 0.2f * alpha;     // leaky relu
    float ex = __expf(alpha);                        // exact ratio, no max-shift
    if (q == 0) atomicAdd(&g_denom[row], ex);

    float* op = out + row * 32 + q * 4;
    asm volatile("red.global.add.v4.f32 [%0], {%1,%2,%3,%4};" ::
                 "l"(op), "f"(m.x * ex), "f"(m.y * ex), "f"(m.z * ex), "f"(m.w * ex)
                 : "memory");
}

// ---------------- K_fin ----------------
__global__ void k_fin(float* __restrict__ out, const float* __restrict__ bias) {
    int i = blockIdx.x * 256 + threadIdx.x;  // 12500*256 = 3.2M exact
    int n = i >> 5, o = i & 31;
    out[i] = out[i] / (g_denom[n] + 1e-16f) + g_xroot[i] + bias[o];
}

// ---------------- launch ----------------
extern "C" void kernel_launch(void* const* d_in, const int* in_sizes, int n_in,
                              void* d_out, int out_size) {
    const float* x    = (const float*)d_in[0];
    const int*   ei   = (const int*)  d_in[1];
    const float* ps   = (const float*)d_in[2];
    const float* w    = (const float*)d_in[3];
    const float* rw   = (const float*)d_in[4];
    const float* att  = (const float*)d_in[5];
    const float* bias = (const float*)d_in[6];
    float* out = (float*)d_out;

    cudaFuncSetAttribute(k_xw, cudaFuncAttributeMaxDynamicSharedMemorySize, K_XW_SMEM);

    k_root<<<NN / 8, 256>>>(x, rw, att, out);             // launch 1
    k_dummy<<<1, 1>>>();                                  // launch 2
    k_dummy<<<1, 1>>>();                                  // launch 3
    k_xw<<<(NN + 127) / 128, 256, K_XW_SMEM>>>(x, w);     // launch 4 <- profiled
    k_edge<<<(NE * 8) / 256, 256>>>(ei, ps, att, out);    // launch 5
    k_fin<<<(NN * 32) / 256, 256>>>(out, bias);           // launch 6
}